// round 2
// baseline (speedup 1.0000x reference)
#include <cuda_runtime.h>
#include <math.h>

#define BB 64
#define SS 512
#define HH 768
#define LL 9

// scratch (no allocations allowed in kernel_launch)
__device__ int   g_src[BB * SS];   // g_src[b*SS + p] = source token s for compacted slot p
__device__ int   g_cnt[BB];        // number of valid tokens per row
__device__ float g_sb[LL];         // softmax(bias) for tail slots

// packed f32x2 fma: d = a*b + c elementwise on two packed floats
__device__ __forceinline__ unsigned long long fma2(unsigned long long a,
                                                   unsigned long long b,
                                                   unsigned long long c) {
    unsigned long long d;
    asm("fma.rn.f32x2 %0, %1, %2, %3;" : "=l"(d) : "l"(a), "l"(b), "l"(c));
    return d;
}
__device__ __forceinline__ float f2sum(unsigned long long a) {
    unsigned lo, hi;
    asm("mov.b64 {%0, %1}, %2;" : "=r"(lo), "=r"(hi) : "l"(a));
    return __uint_as_float(lo) + __uint_as_float(hi);
}

// ---------------------------------------------------------------------------
// Kernel 1: ballot-based per-row scan of valid_mask -> gather idx + counts.
// ---------------------------------------------------------------------------
__global__ void __launch_bounds__(SS) ner_scan_kernel(const int* __restrict__ mask,
                                                      const float* __restrict__ bias) {
    __shared__ int wsum[16];
    const int b = blockIdx.x;
    const int s = threadIdx.x;
    const int lane = s & 31;
    const int wid  = s >> 5;
    const int m = mask[b * SS + s];
    const unsigned bal = __ballot_sync(0xffffffffu, m != 0);
    const int pre = __popc(bal & ((1u << lane) - 1u));   // exclusive prefix in warp
    if (lane == 31) wsum[wid] = __popc(bal);
    __syncthreads();
    if (wid == 0 && lane < 16) {
        int v = wsum[lane];
#pragma unroll
        for (int off = 1; off < 16; off <<= 1) {
            int u = __shfl_up_sync(0xffffu, v, off);
            if (lane >= off) v += u;
        }
        wsum[lane] = v;   // inclusive scan of warp sums
    }
    __syncthreads();
    const int offset = wid ? wsum[wid - 1] : 0;
    if (m) g_src[b * SS + offset + pre] = s;
    if (s == SS - 1) g_cnt[b] = offset + pre + (m ? 1 : 0);

    if (b == 0 && s == 0) {
        float t[LL];
        float mx = -1e30f;
#pragma unroll
        for (int j = 0; j < LL; j++) { t[j] = bias[j]; mx = fmaxf(mx, t[j]); }
        float sum = 0.f;
#pragma unroll
        for (int j = 0; j < LL; j++) { t[j] = __expf(t[j] - mx); sum += t[j]; }
        const float inv = 1.f / sum;
#pragma unroll
        for (int j = 0; j < LL; j++) g_sb[j] = t[j] * inv;
    }
}

// ---------------------------------------------------------------------------
// Kernel 2: 512-thread blocks, 16 warps, 2 compacted slots per warp.
// f32x2 packed accumulators halve FFMA issue count.
// Grid: 32768 slots / 32 slots-per-block = 1024 blocks.
// ---------------------------------------------------------------------------
__global__ void __launch_bounds__(512, 2) ner_main_kernel(const float* __restrict__ X,
                                                          const float* __restrict__ W,
                                                          const float* __restrict__ bias,
                                                          float* __restrict__ out) {
    __shared__ float sWt[LL * HH];  // transposed: sWt[j*HH + k] = W[k*LL + j]
    const int tid = threadIdx.x;
    for (int idx = tid; idx < LL * HH; idx += 512) {
        const int k = idx / LL;
        const int j = idx - k * LL;
        sWt[j * HH + k] = W[idx];
    }
    __syncthreads();

    const int warp = blockIdx.x * 16 + (tid >> 5);
    const int lane = tid & 31;
    const int t0   = warp * 2;           // first global slot index (b*SS + p)
    const int bi   = t0 >> 9;            // SS = 512
    const int p0   = t0 & (SS - 1);
    const int cnt  = g_cnt[bi];

    if (p0 >= cnt) {                      // both slots are tail
        if (lane < LL) {
            const float v = g_sb[lane];
            out[(size_t)t0 * LL + lane]       = v;
            out[(size_t)(t0 + 1) * LL + lane] = v;
        }
        return;
    }

    const int nv = min(2, cnt - p0);
    const int s0 = g_src[bi * SS + p0];
    const int s1 = g_src[bi * SS + p0 + ((nv > 1) ? 1 : 0)];
    const ulonglong2* xp0 = (const ulonglong2*)(X + ((size_t)bi * SS + s0) * HH);
    const ulonglong2* xp1 = (const ulonglong2*)(X + ((size_t)bi * SS + s1) * HH);

    unsigned long long a0[LL], a1[LL];
#pragma unroll
    for (int j = 0; j < LL; j++) { a0[j] = 0ull; a1[j] = 0ull; }

#pragma unroll
    for (int it = 0; it < HH / 128; it++) {   // 6 iterations, 128 floats/warp each
        const int k4 = it * 32 + lane;        // 16B-chunk index within row (192 total)
        const ulonglong2 x0 = xp0[k4];
        const ulonglong2 x1 = xp1[k4];
#pragma unroll
        for (int j = 0; j < LL; j++) {
            const ulonglong2 w = *(const ulonglong2*)(sWt + j * HH + k4 * 4);
            a0[j] = fma2(x0.x, w.x, a0[j]);
            a0[j] = fma2(x0.y, w.y, a0[j]);
            a1[j] = fma2(x1.x, w.x, a1[j]);
            a1[j] = fma2(x1.y, w.y, a1[j]);
        }
    }

    float v0[LL], v1[LL];
#pragma unroll
    for (int j = 0; j < LL; j++) {
        float u = f2sum(a0[j]);
        float w = f2sum(a1[j]);
        u += __shfl_xor_sync(0xffffffffu, u, 16);
        u += __shfl_xor_sync(0xffffffffu, u, 8);
        u += __shfl_xor_sync(0xffffffffu, u, 4);
        u += __shfl_xor_sync(0xffffffffu, u, 2);
        u += __shfl_xor_sync(0xffffffffu, u, 1);
        w += __shfl_xor_sync(0xffffffffu, w, 16);
        w += __shfl_xor_sync(0xffffffffu, w, 8);
        w += __shfl_xor_sync(0xffffffffu, w, 4);
        w += __shfl_xor_sync(0xffffffffu, w, 2);
        w += __shfl_xor_sync(0xffffffffu, w, 1);
        v0[j] = u;
        v1[j] = w;
    }

    // token 0 (always valid)
    {
        float mx = -1e30f;
#pragma unroll
        for (int j = 0; j < LL; j++) { v0[j] += bias[j]; mx = fmaxf(mx, v0[j]); }
        float sum = 0.f;
#pragma unroll
        for (int j = 0; j < LL; j++) { v0[j] = __expf(v0[j] - mx); sum += v0[j]; }
        const float inv = 1.f / sum;
        if (lane < LL) out[(size_t)t0 * LL + lane] = v0[lane] * inv;
    }
    // token 1
    if (nv > 1) {
        float mx = -1e30f;
#pragma unroll
        for (int j = 0; j < LL; j++) { v1[j] += bias[j]; mx = fmaxf(mx, v1[j]); }
        float sum = 0.f;
#pragma unroll
        for (int j = 0; j < LL; j++) { v1[j] = __expf(v1[j] - mx); sum += v1[j]; }
        const float inv = 1.f / sum;
        if (lane < LL) out[(size_t)(t0 + 1) * LL + lane] = v1[lane] * inv;
    } else {
        if (lane < LL) out[(size_t)(t0 + 1) * LL + lane] = g_sb[lane];
    }
}

// ---------------------------------------------------------------------------
extern "C" void kernel_launch(void* const* d_in, const int* in_sizes, int n_in,
                              void* d_out, int out_size) {
    const float* seq  = nullptr;  // [64,512,768] f32
    const int*   mask = nullptr;  // [64,512]     i32
    const float* W    = nullptr;  // [768,9]      f32
    const float* bias = nullptr;  // [9]          f32
    for (int i = 0; i < n_in; i++) {
        switch (in_sizes[i]) {
            case BB * SS * HH: seq  = (const float*)d_in[i]; break;
            case BB * SS:      mask = (const int*)d_in[i];   break;
            case HH * LL:      W    = (const float*)d_in[i]; break;
            case LL:           bias = (const float*)d_in[i]; break;
        }
    }
    float* out = (float*)d_out;

    ner_scan_kernel<<<BB, SS>>>(mask, bias);
    // 32768 slots, 2 slots/warp, 16 warps/block -> 1024 blocks x 512 threads
    ner_main_kernel<<<(BB * SS) / 32, 512>>>(seq, W, bias, out);
}

// round 4
// speedup vs baseline: 1.2730x; 1.2730x over previous
#include <cuda_runtime.h>
#include <math.h>

#define BB 64
#define SS 512
#define HH 768
#define LL 9

// scratch (no allocations allowed in kernel_launch)
__device__ int   g_src[BB * SS];   // g_src[b*SS + p] = source token s for compacted slot p
__device__ int   g_cnt[BB];        // number of valid tokens per row
__device__ float g_sb[LL];         // softmax(bias) for tail slots
__device__ float g_Wt[LL * HH];    // W transposed: g_Wt[j*HH + k] = W[k*LL + j]

// packed f32x2 fma: d = a*b + c elementwise on two packed floats
__device__ __forceinline__ unsigned long long fma2(unsigned long long a,
                                                   unsigned long long b,
                                                   unsigned long long c) {
    unsigned long long d;
    asm("fma.rn.f32x2 %0, %1, %2, %3;" : "=l"(d) : "l"(a), "l"(b), "l"(c));
    return d;
}
__device__ __forceinline__ float f2sum(unsigned long long a) {
    unsigned lo, hi;
    asm("mov.b64 {%0, %1}, %2;" : "=r"(lo), "=r"(hi) : "l"(a));
    return __uint_as_float(lo) + __uint_as_float(hi);
}

// ---------------------------------------------------------------------------
// Kernel 1: ballot-based per-row scan of valid_mask -> gather idx + counts.
// Also: transpose W into g_Wt (spread across blocks), precompute softmax(bias).
// ---------------------------------------------------------------------------
__global__ void __launch_bounds__(SS) ner_scan_kernel(const int* __restrict__ mask,
                                                      const float* __restrict__ W,
                                                      const float* __restrict__ bias) {
    __shared__ int wsum[16];
    const int b = blockIdx.x;
    const int s = threadIdx.x;
    const int lane = s & 31;
    const int wid  = s >> 5;
    const int m = mask[b * SS + s];
    const unsigned bal = __ballot_sync(0xffffffffu, m != 0);
    const int pre = __popc(bal & ((1u << lane) - 1u));   // exclusive prefix in warp
    if (lane == 31) wsum[wid] = __popc(bal);

    // transpose a 108-element slice of W (64 blocks x 108 >= 6912 = LL*HH)
    {
        const int idx = b * 108 + s;
        if (s < 108 && idx < LL * HH) {
            const int k = idx / LL;
            const int j = idx - k * LL;
            g_Wt[j * HH + k] = W[idx];
        }
    }

    __syncthreads();
    if (wid == 0 && lane < 16) {
        int v = wsum[lane];
#pragma unroll
        for (int off = 1; off < 16; off <<= 1) {
            int u = __shfl_up_sync(0xffffu, v, off);
            if (lane >= off) v += u;
        }
        wsum[lane] = v;   // inclusive scan of warp sums
    }
    __syncthreads();
    const int offset = wid ? wsum[wid - 1] : 0;
    if (m) g_src[b * SS + offset + pre] = s;
    if (s == SS - 1) g_cnt[b] = offset + pre + (m ? 1 : 0);

    if (b == 0 && s == 0) {
        float t[LL];
        float mx = -1e30f;
#pragma unroll
        for (int j = 0; j < LL; j++) { t[j] = bias[j]; mx = fmaxf(mx, t[j]); }
        float sum = 0.f;
#pragma unroll
        for (int j = 0; j < LL; j++) { t[j] = __expf(t[j] - mx); sum += t[j]; }
        const float inv = 1.f / sum;
#pragma unroll
        for (int j = 0; j < LL; j++) g_sb[j] = t[j] * inv;
    }
}

// ---------------------------------------------------------------------------
// Kernel 2: 256-thread blocks, 8 warps, 4 compacted slots per warp
// (32 slots/block, all within one batch row). f32x2 packed accumulators.
// All-tail blocks exit before touching shared memory (block-uniform branch,
// so the skipped __syncthreads is safe).
// Grid: 32768 / 32 = 1024 blocks.
// ---------------------------------------------------------------------------
__global__ void __launch_bounds__(256, 2) ner_main_kernel(const float* __restrict__ X,
                                                          const float* __restrict__ bias,
                                                          float* __restrict__ out) {
    const int tid  = threadIdx.x;
    const int lane = tid & 31;
    const int tb   = blockIdx.x * 32;     // first slot of this block
    const int bi   = tb >> 9;             // SS = 512
    const int pb   = tb & (SS - 1);
    const int cnt  = g_cnt[bi];

    if (pb >= cnt) {                      // whole block is tail
        const int warp = tid >> 5;
        const int t0   = tb + warp * 4;
        if (lane < LL) {
            const float v = g_sb[lane];
#pragma unroll
            for (int i = 0; i < 4; i++)
                out[(size_t)(t0 + i) * LL + lane] = v;
        }
        return;
    }

    __shared__ float sWt[LL * HH];        // straight copy of pre-transposed W
    {
        const float4* src = (const float4*)g_Wt;
        float4* dst = (float4*)sWt;
        for (int i = tid; i < (LL * HH) / 4; i += 256) dst[i] = src[i];
    }
    __syncthreads();

    const int warp = tid >> 5;
    const int t0   = tb + warp * 4;
    const int p0   = t0 & (SS - 1);

    if (p0 >= cnt) {                      // tail warp within a mixed block
        if (lane < LL) {
            const float v = g_sb[lane];
#pragma unroll
            for (int i = 0; i < 4; i++)
                out[(size_t)(t0 + i) * LL + lane] = v;
        }
        return;
    }

    const int nv = min(4, cnt - p0);
    const ulonglong2* xp[4];
#pragma unroll
    for (int i = 0; i < 4; i++) {
        const int pi = p0 + ((i < nv) ? i : 0);   // clamp (discarded later)
        const int s  = g_src[bi * SS + pi];
        xp[i] = (const ulonglong2*)(X + ((size_t)bi * SS + s) * HH);
    }

    unsigned long long acc[4][LL];
#pragma unroll
    for (int i = 0; i < 4; i++)
#pragma unroll
        for (int j = 0; j < LL; j++) acc[i][j] = 0ull;

#pragma unroll
    for (int it = 0; it < HH / 128; it++) {   // 6 iterations, 16B/lane each
        const int k4 = it * 32 + lane;        // 16B-chunk index (192 per row)
        const ulonglong2 x0 = xp[0][k4];
        const ulonglong2 x1 = xp[1][k4];
        const ulonglong2 x2 = xp[2][k4];
        const ulonglong2 x3 = xp[3][k4];
#pragma unroll
        for (int j = 0; j < LL; j++) {
            const ulonglong2 w = *(const ulonglong2*)(sWt + j * HH + k4 * 4);
            acc[0][j] = fma2(x0.x, w.x, acc[0][j]);
            acc[0][j] = fma2(x0.y, w.y, acc[0][j]);
            acc[1][j] = fma2(x1.x, w.x, acc[1][j]);
            acc[1][j] = fma2(x1.y, w.y, acc[1][j]);
            acc[2][j] = fma2(x2.x, w.x, acc[2][j]);
            acc[2][j] = fma2(x2.y, w.y, acc[2][j]);
            acc[3][j] = fma2(x3.x, w.x, acc[3][j]);
            acc[3][j] = fma2(x3.y, w.y, acc[3][j]);
        }
    }

    // warp reduction: every lane ends with the full sums
    float v[4][LL];
#pragma unroll
    for (int i = 0; i < 4; i++)
#pragma unroll
        for (int j = 0; j < LL; j++) {
            float u = f2sum(acc[i][j]);
            u += __shfl_xor_sync(0xffffffffu, u, 16);
            u += __shfl_xor_sync(0xffffffffu, u, 8);
            u += __shfl_xor_sync(0xffffffffu, u, 4);
            u += __shfl_xor_sync(0xffffffffu, u, 2);
            u += __shfl_xor_sync(0xffffffffu, u, 1);
            v[i][j] = u;
        }

#pragma unroll
    for (int i = 0; i < 4; i++) {
        if (i < nv) {
            float mx = -1e30f;
#pragma unroll
            for (int j = 0; j < LL; j++) { v[i][j] += bias[j]; mx = fmaxf(mx, v[i][j]); }
            float sum = 0.f;
#pragma unroll
            for (int j = 0; j < LL; j++) { v[i][j] = __expf(v[i][j] - mx); sum += v[i][j]; }
            const float inv = 1.f / sum;
            if (lane < LL) out[(size_t)(t0 + i) * LL + lane] = v[i][lane] * inv;
        } else {
            if (lane < LL) out[(size_t)(t0 + i) * LL + lane] = g_sb[lane];
        }
    }
}

// ---------------------------------------------------------------------------
extern "C" void kernel_launch(void* const* d_in, const int* in_sizes, int n_in,
                              void* d_out, int out_size) {
    const float* seq  = nullptr;  // [64,512,768] f32
    const int*   mask = nullptr;  // [64,512]     i32
    const float* W    = nullptr;  // [768,9]      f32
    const float* bias = nullptr;  // [9]          f32
    for (int i = 0; i < n_in; i++) {
        switch (in_sizes[i]) {
            case BB * SS * HH: seq  = (const float*)d_in[i]; break;
            case BB * SS:      mask = (const int*)d_in[i];   break;
            case HH * LL:      W    = (const float*)d_in[i]; break;
            case LL:           bias = (const float*)d_in[i]; break;
        }
    }
    float* out = (float*)d_out;

    ner_scan_kernel<<<BB, SS>>>(mask, W, bias);
    // 32768 slots, 4 slots/warp, 8 warps/block -> 1024 blocks x 256 threads
    ner_main_kernel<<<(BB * SS) / 32, 256>>>(seq, bias, out);
}

// round 6
// speedup vs baseline: 1.2944x; 1.0169x over previous
#include <cuda_runtime.h>
#include <math.h>

#define BB 64
#define SS 512
#define HH 768
#define LL 9

// scratch (no allocations allowed in kernel_launch)
__device__ int   g_src[BB * SS];   // g_src[b*SS + p] = source token s for compacted slot p
__device__ int   g_cnt[BB];        // number of valid tokens per row
__device__ float g_sb[LL];         // softmax(bias) for tail slots
__device__ float g_Wt[LL * HH];    // W transposed: g_Wt[j*HH + k] = W[k*LL + j]

// ---------------------------------------------------------------------------
// Kernel 1: ballot-based per-row scan of valid_mask -> gather idx + counts.
// Also: transpose W into g_Wt (spread across blocks), precompute softmax(bias).
// ---------------------------------------------------------------------------
__global__ void __launch_bounds__(SS) ner_scan_kernel(const int* __restrict__ mask,
                                                      const float* __restrict__ W,
                                                      const float* __restrict__ bias) {
    __shared__ int wsum[16];
    const int b = blockIdx.x;
    const int s = threadIdx.x;
    const int lane = s & 31;
    const int wid  = s >> 5;
    const int m = mask[b * SS + s];
    const unsigned bal = __ballot_sync(0xffffffffu, m != 0);
    const int pre = __popc(bal & ((1u << lane) - 1u));   // exclusive prefix in warp
    if (lane == 31) wsum[wid] = __popc(bal);

    // transpose a 108-element slice of W (64 blocks x 108 >= 6912 = LL*HH)
    {
        const int idx = b * 108 + s;
        if (s < 108 && idx < LL * HH) {
            const int k = idx / LL;
            const int j = idx - k * LL;
            g_Wt[j * HH + k] = W[idx];
        }
    }

    __syncthreads();
    if (wid == 0 && lane < 16) {
        int v = wsum[lane];
#pragma unroll
        for (int off = 1; off < 16; off <<= 1) {
            int u = __shfl_up_sync(0xffffu, v, off);
            if (lane >= off) v += u;
        }
        wsum[lane] = v;   // inclusive scan of warp sums
    }
    __syncthreads();
    const int offset = wid ? wsum[wid - 1] : 0;
    if (m) g_src[b * SS + offset + pre] = s;
    if (s == SS - 1) g_cnt[b] = offset + pre + (m ? 1 : 0);

    if (b == 0 && s == 0) {
        float t[LL];
        float mx = -1e30f;
#pragma unroll
        for (int j = 0; j < LL; j++) { t[j] = bias[j]; mx = fmaxf(mx, t[j]); }
        float sum = 0.f;
#pragma unroll
        for (int j = 0; j < LL; j++) { t[j] = __expf(t[j] - mx); sum += t[j]; }
        const float inv = 1.f / sum;
#pragma unroll
        for (int j = 0; j < LL; j++) g_sb[j] = t[j] * inv;
    }
}

// ---------------------------------------------------------------------------
// Kernel 2: 256-thread blocks, 8 warps, 4 compacted slots per warp.
// Plain f32 accumulators (36 regs) + explicit 2-stage load prefetch to
// maximize memory-level parallelism. All-tail blocks exit before smem.
// Grid: 32768 / 32 = 1024 blocks.
// ---------------------------------------------------------------------------
__global__ void __launch_bounds__(256, 2) ner_main_kernel(const float* __restrict__ X,
                                                          const float* __restrict__ bias,
                                                          float* __restrict__ out) {
    const int tid  = threadIdx.x;
    const int lane = tid & 31;
    const int tb   = blockIdx.x * 32;     // first slot of this block
    const int bi   = tb >> 9;             // SS = 512
    const int pb   = tb & (SS - 1);
    const int cnt  = g_cnt[bi];

    if (pb >= cnt) {                      // whole block is tail (block-uniform)
        const int warp = tid >> 5;
        const int t0   = tb + warp * 4;
        if (lane < LL) {
            const float v = g_sb[lane];
#pragma unroll
            for (int i = 0; i < 4; i++)
                out[(size_t)(t0 + i) * LL + lane] = v;
        }
        return;
    }

    const int warp = tid >> 5;
    const int t0   = tb + warp * 4;
    const int p0   = t0 & (SS - 1);
    const bool live = (p0 < cnt);
    const int nv   = live ? min(4, cnt - p0) : 0;

    // gather pointers set up BEFORE the smem copy so first X loads overlap it
    const float4* xp0 = nullptr;
    const float4* xp1 = nullptr;
    const float4* xp2 = nullptr;
    const float4* xp3 = nullptr;
    float4 c0, c1, c2, c3;
    if (live) {
        const int i1 = (nv > 1) ? 1 : 0;
        const int i2 = (nv > 2) ? 2 : 0;
        const int i3 = (nv > 3) ? 3 : 0;
        xp0 = (const float4*)(X + ((size_t)bi * SS + g_src[bi * SS + p0]) * HH);
        xp1 = (const float4*)(X + ((size_t)bi * SS + g_src[bi * SS + p0 + i1]) * HH);
        xp2 = (const float4*)(X + ((size_t)bi * SS + g_src[bi * SS + p0 + i2]) * HH);
        xp3 = (const float4*)(X + ((size_t)bi * SS + g_src[bi * SS + p0 + i3]) * HH);
        c0 = xp0[lane]; c1 = xp1[lane]; c2 = xp2[lane]; c3 = xp3[lane];
    }

    __shared__ float sWt[LL * HH];        // straight copy of pre-transposed W
    {
        const float4* src = (const float4*)g_Wt;
        float4* dst = (float4*)sWt;
        for (int i = tid; i < (LL * HH) / 4; i += 256) dst[i] = src[i];
    }
    __syncthreads();

    if (!live) {                          // tail warp within a mixed block
        if (lane < LL) {
            const float v = g_sb[lane];
#pragma unroll
            for (int i = 0; i < 4; i++)
                out[(size_t)(t0 + i) * LL + lane] = v;
        }
        return;
    }

    float acc[4][LL];
#pragma unroll
    for (int i = 0; i < 4; i++)
#pragma unroll
        for (int j = 0; j < LL; j++) acc[i][j] = 0.f;

#pragma unroll
    for (int it = 0; it < HH / 128; it++) {   // 6 iterations, 16B/lane each
        const int k4 = it * 32 + lane;
        // prefetch next iteration's data before this iteration's FMA chain
        float4 n0, n1, n2, n3;
        if (it < HH / 128 - 1) {
            const int kn = k4 + 32;
            n0 = xp0[kn]; n1 = xp1[kn]; n2 = xp2[kn]; n3 = xp3[kn];
        }
#pragma unroll
        for (int j = 0; j < LL; j++) {
            const float4 w = *(const float4*)(sWt + j * HH + k4 * 4);
            acc[0][j] += c0.x * w.x + c0.y * w.y + c0.z * w.z + c0.w * w.w;
            acc[1][j] += c1.x * w.x + c1.y * w.y + c1.z * w.z + c1.w * w.w;
            acc[2][j] += c2.x * w.x + c2.y * w.y + c2.z * w.z + c2.w * w.w;
            acc[3][j] += c3.x * w.x + c3.y * w.y + c3.z * w.z + c3.w * w.w;
        }
        if (it < HH / 128 - 1) { c0 = n0; c1 = n1; c2 = n2; c3 = n3; }
    }

    // warp reduction: every lane ends with the full sums
#pragma unroll
    for (int i = 0; i < 4; i++)
#pragma unroll
        for (int j = 0; j < LL; j++) {
            float u = acc[i][j];
            u += __shfl_xor_sync(0xffffffffu, u, 16);
            u += __shfl_xor_sync(0xffffffffu, u, 8);
            u += __shfl_xor_sync(0xffffffffu, u, 4);
            u += __shfl_xor_sync(0xffffffffu, u, 2);
            u += __shfl_xor_sync(0xffffffffu, u, 1);
            acc[i][j] = u;
        }

#pragma unroll
    for (int i = 0; i < 4; i++) {
        if (i < nv) {
            float l[LL];
            float mx = -1e30f;
#pragma unroll
            for (int j = 0; j < LL; j++) { l[j] = acc[i][j] + bias[j]; mx = fmaxf(mx, l[j]); }
            float sum = 0.f;
#pragma unroll
            for (int j = 0; j < LL; j++) { l[j] = __expf(l[j] - mx); sum += l[j]; }
            const float inv = 1.f / sum;
            if (lane < LL) out[(size_t)(t0 + i) * LL + lane] = l[lane] * inv;
        } else {
            if (lane < LL) out[(size_t)(t0 + i) * LL + lane] = g_sb[lane];
        }
    }
}

// ---------------------------------------------------------------------------
extern "C" void kernel_launch(void* const* d_in, const int* in_sizes, int n_in,
                              void* d_out, int out_size) {
    const float* seq  = nullptr;  // [64,512,768] f32
    const int*   mask = nullptr;  // [64,512]     i32
    const float* W    = nullptr;  // [768,9]      f32
    const float* bias = nullptr;  // [9]          f32
    for (int i = 0; i < n_in; i++) {
        switch (in_sizes[i]) {
            case BB * SS * HH: seq  = (const float*)d_in[i]; break;
            case BB * SS:      mask = (const int*)d_in[i];   break;
            case HH * LL:      W    = (const float*)d_in[i]; break;
            case LL:           bias = (const float*)d_in[i]; break;
        }
    }
    float* out = (float*)d_out;

    ner_scan_kernel<<<BB, SS>>>(mask, W, bias);
    // 32768 slots, 4 slots/warp, 8 warps/block -> 1024 blocks x 256 threads
    ner_main_kernel<<<(BB * SS) / 32, 256>>>(seq, bias, out);
}